// round 5
// baseline (speedup 1.0000x reference)
#include <cuda_runtime.h>
#include <cstdint>

#define BATCH 16
#define HH 56
#define WW 56
#define EPSV 1e-5f

// ---------------- scratch (device globals; no allocation) ----------------
__device__ uint32_t g_Abits[BATCH * 8 * HH * WW];    // stage1 input bits  [b][w][y][x]
__device__ uint32_t g_Sbits[BATCH * 16 * HH * WW];   // stage2 input bits  [b][w][y][x]
__device__ float    g_Out1f[BATCH * 128 * HH * WW];  // out1 channels 0..127
__device__ uint32_t g_W1b[72 * 256];                 // [k][oc]
__device__ uint32_t g_W2b[144 * 256];                // permuted for shuffle
__device__ int      g_NW1[9 * 256];
__device__ int      g_NW2[9 * 256];
__device__ float    g_alpha1[256], g_c1[256], g_alpha2[256], g_c2[256];

// ---------------- weight prep ----------------
__global__ void prep_w1(const float* __restrict__ w1, const float* __restrict__ gm,
                        const float* __restrict__ bt, const float* __restrict__ mn,
                        const float* __restrict__ vr) {
    int oc = blockIdx.x;
    int c  = threadIdx.x;
    int lane = c & 31, wi = c >> 5;
    __shared__ int nw[9];
    __shared__ float red[8];
    if (c < 9) nw[c] = 0;
    __syncthreads();
    float asum = 0.f;
#pragma unroll
    for (int r = 0; r < 3; r++)
#pragma unroll
        for (int dx = 0; dx < 3; dx++) {
            float v = w1[((oc * 256 + c) * 3 + r) * 3 + dx];
            asum += fabsf(v);
            unsigned word = __ballot_sync(0xffffffffu, v < 0.f);
            if (lane == 0) {
                int k = (wi * 3 + r) * 3 + dx;
                g_W1b[k * 256 + oc] = word;
                atomicAdd(&nw[r * 3 + dx], __popc(word));
            }
        }
    __syncthreads();
    if (c < 9) g_NW1[c * 256 + oc] = nw[c];
    for (int o = 16; o > 0; o >>= 1) asum += __shfl_xor_sync(0xffffffffu, asum, o);
    if (lane == 0) red[wi] = asum;
    __syncthreads();
    if (c == 0) {
        float s = 0.f;
#pragma unroll
        for (int i = 0; i < 8; i++) s += red[i];
        float scale = s / (256.f * 9.f);
        float inv = gm[oc] / sqrtf(vr[oc] + EPSV);
        g_alpha1[oc] = scale * inv;
        g_c1[oc] = bt[oc] - mn[oc] * inv;
    }
}

__global__ void prep_w2(const float* __restrict__ w2, const float* __restrict__ gm,
                        const float* __restrict__ bt, const float* __restrict__ mn,
                        const float* __restrict__ vr) {
    int oc = blockIdx.x;
    int c  = threadIdx.x;
    int lane = c & 31;
    __shared__ int nw[9];
    __shared__ float red[8];
    if (c < 9) nw[c] = 0;
    __syncthreads();
    float asum = 0.f;
    for (int it = 0; it < 2; it++) {
        int j  = it * 256 + c;
        int ic = (j < 256) ? (2 * j) : (2 * (j - 256) + 1);
        int wi = j >> 5;
#pragma unroll
        for (int r = 0; r < 3; r++)
#pragma unroll
            for (int dx = 0; dx < 3; dx++) {
                float v = w2[((oc * 512 + ic) * 3 + r) * 3 + dx];
                asum += fabsf(v);
                unsigned word = __ballot_sync(0xffffffffu, v < 0.f);
                if (lane == 0) {
                    int k = (wi * 3 + r) * 3 + dx;
                    g_W2b[k * 256 + oc] = word;
                    atomicAdd(&nw[r * 3 + dx], __popc(word));
                }
            }
    }
    __syncthreads();
    if (c < 9) g_NW2[c * 256 + oc] = nw[c];
    for (int o = 16; o > 0; o >>= 1) asum += __shfl_xor_sync(0xffffffffu, asum, o);
    if (lane == 0) red[c >> 5] = asum;
    __syncthreads();
    if (c == 0) {
        float s = 0.f;
#pragma unroll
        for (int i = 0; i < 8; i++) s += red[i];
        float scale = s / (512.f * 9.f);
        float inv = gm[oc] / sqrtf(vr[oc] + EPSV);
        g_alpha2[oc] = scale * inv;
        g_c2[oc] = bt[oc] - mn[oc] * inv;
    }
}

// ---------------- input packing ----------------
__global__ void pack_input(const float* __restrict__ x, const float* __restrict__ mb) {
    int n = blockIdx.x * blockDim.x + threadIdx.x;
    if (n >= BATCH * HH * WW) return;
    int xw = n % (HH * WW);
    int b  = n / (HH * WW);
    const float* xp = x + (size_t)b * 512 * HH * WW + xw;
#pragma unroll 1
    for (int wi = 0; wi < 8; wi++) {
        uint32_t word = 0;
#pragma unroll
        for (int k = 0; k < 32; k++) {
            float v = __ldg(&xp[(size_t)(wi * 32 + k) * HH * WW]);
            word |= (v < 0.f ? 1u : 0u) << k;
        }
        g_Abits[(b * 8 + wi) * HH * WW + xw] = word;
    }
#pragma unroll 1
    for (int wi = 0; wi < 8; wi++) {
        uint32_t word = 0;
#pragma unroll
        for (int k = 0; k < 32; k++) {
            int ci = wi * 32 + k;
            float v = __ldg(&xp[(size_t)(256 + ci) * HH * WW]) + __ldg(&mb[ci]);
            word |= (v < 0.f ? 1u : 0u) << k;
        }
        g_Sbits[(b * 16 + (8 + wi)) * HH * WW + xw] = word;
    }
}

__device__ __forceinline__ uint32_t maj3(uint32_t a, uint32_t b, uint32_t c) {
    return (a & b) | (b & c) | (a & c);   // single LOP3, LUT 0xE8
}
__device__ __forceinline__ uint32_t xor3(uint32_t a, uint32_t b, uint32_t c) {
    return a ^ b ^ c;                      // single LOP3, LUT 0x96
}

// ---------------- binarized conv (XOR + 9:4 CSA popcount) ----------------
// Block: 256 threads; tile = 56 px (one row) x 64 oc. Thread: 7 px x 2 oc.
// Full 3x3 window CSA tree: 9 taps -> 4 popcounts, weights 1/2/2/4.
// Packed acc fields: bit0 (S1, <=512), bit10 (C1+S2, <=1024), bit21 (C2, <=512).
template <int WORDS, int STAGE>
__global__ __launch_bounds__(256, 4) void binconv(const float* __restrict__ x,
                                                  const float* __restrict__ mb,
                                                  float* __restrict__ out) {
    constexpr int K = WORDS * 9;
    constexpr int CTOT = WORDS * 32;
    extern __shared__ uint32_t smem[];
    uint32_t* Ws = smem;                          // [K][64]  (reused post-mainloop)
    uint32_t* As = smem + K * 64;                 // [WORDS*3][58]
    float*    Rs = (float*)(As + WORDS * 3 * 58); // stage1: [64][57] residual -> Vs
    float*    Vs = (STAGE == 1) ? Rs : (float*)Ws;
    uint32_t* stg = Ws;                           // stage1 sign-bit staging

    const uint32_t* Gb = (STAGE == 1) ? g_Abits : g_Sbits;
    const uint32_t* Wg = (STAGE == 1) ? g_W1b : g_W2b;

    int ocq = blockIdx.x;        // oc quarter (64 oc)
    int y = blockIdx.y;
    int b = blockIdx.z;
    int tid = threadIdx.x;
    int og = tid & 31;           // lane: oc pair index
    int g  = tid >> 5;           // warp: pixel group (7 px)

    // ---- cooperative loads ----
    for (int idx = tid; idx < K * 64; idx += 256) {
        int k = idx >> 6, o = idx & 63;
        Ws[idx] = Wg[k * 256 + ocq * 64 + o];
    }
    for (int idx = tid; idx < WORDS * 3 * 58; idx += 256) {
        int c = idx % 58;
        int wr = idx / 58;
        int r = wr % 3, w = wr / 3;
        int yy = y + r - 1;
        int xx = c - 1;
        uint32_t v = 0;
        if ((unsigned)yy < HH && (unsigned)xx < WW)
            v = Gb[((b * WORDS + w) * HH + yy) * WW + xx];
        As[wr * 58 + c] = v;
    }
    if (STAGE == 1) {
        for (int idx = tid; idx < 64 * WW; idx += 256) {
            int oc_l = idx / WW, px = idx % WW;
            Rs[oc_l * 57 + px] =
                __ldg(&x[(((size_t)b * 512 + ocq * 64 + oc_l) * HH + y) * WW + px]);
        }
    }
    __syncthreads();

    // ---- main loop ----
    uint32_t acc[7][2];
#pragma unroll
    for (int p = 0; p < 7; p++) { acc[p][0] = 0; acc[p][1] = 0; }

#pragma unroll 1
    for (int w = 0; w < WORDS; w++) {
        uint32_t a[3][9];
#pragma unroll
        for (int r = 0; r < 3; r++) {
            const uint32_t* arow = &As[(w * 3 + r) * 58 + 7 * g];
#pragma unroll
            for (int i = 0; i < 9; i++) a[r][i] = arow[i];
        }
#pragma unroll
        for (int j = 0; j < 2; j++) {
            uint32_t wr_[9];
#pragma unroll
            for (int k = 0; k < 9; k++) wr_[k] = Ws[(w * 9 + k) * 64 + og * 2 + j];
#pragma unroll
            for (int p = 0; p < 7; p++) {
                uint32_t s0, c0, s1, c1, s2, c2;
                {
                    uint32_t x0 = a[0][p] ^ wr_[0], x1 = a[0][p + 1] ^ wr_[1], x2 = a[0][p + 2] ^ wr_[2];
                    s0 = xor3(x0, x1, x2); c0 = maj3(x0, x1, x2);
                }
                {
                    uint32_t x0 = a[1][p] ^ wr_[3], x1 = a[1][p + 1] ^ wr_[4], x2 = a[1][p + 2] ^ wr_[5];
                    s1 = xor3(x0, x1, x2); c1 = maj3(x0, x1, x2);
                }
                {
                    uint32_t x0 = a[2][p] ^ wr_[6], x1 = a[2][p + 1] ^ wr_[7], x2 = a[2][p + 2] ^ wr_[8];
                    s2 = xor3(x0, x1, x2); c2 = maj3(x0, x1, x2);
                }
                uint32_t S1 = xor3(s0, s1, s2), C1 = maj3(s0, s1, s2);
                uint32_t S2 = xor3(c0, c1, c2), C2 = maj3(c0, c1, c2);
                uint32_t t = acc[p][j];
                t += __popc(S1);                        // IADD (alu)
                t = __popc(C1) * 1024u + t;             // IMAD (fma)
                t = __popc(S2) * 1024u + t;             // IMAD (fma)
                t = __popc(C2) * (1u << 21) + t;        // IMAD (fma)
                acc[p][j] = t;
            }
        }
    }
    __syncthreads();   // Ws reads done; region reusable

    // ---- epilogue ----
    int ocbase = ocq * 64 + og * 2;
    const float* Ag = (STAGE == 1) ? g_alpha1 : g_alpha2;
    const float* Cg = (STAGE == 1) ? g_c1 : g_c2;
    const int* NWg = (STAGE == 1) ? g_NW1 : g_NW2;
    float alpha[2], cc[2];
#pragma unroll
    for (int j = 0; j < 2; j++) { alpha[j] = __ldg(&Ag[ocbase + j]); cc[j] = __ldg(&Cg[ocbase + j]); }
    bool ybord = (y == 0) || (y == HH - 1);

#pragma unroll
    for (int p = 0; p < 7; p++) {
        int xx = 7 * g + p;
        bool bord = ybord || (xx == 0) || (xx == WW - 1);
        int nv = 9;
        int corr[2] = {0, 0};
        if (bord) {
#pragma unroll
            for (int t = 0; t < 9; t++) {
                int dy = t / 3 - 1, dx = t % 3 - 1;
                if ((unsigned)(y + dy) >= HH || (unsigned)(xx + dx) >= WW) {
                    nv--;
                    corr[0] += __ldg(&NWg[t * 256 + ocbase]);
                    corr[1] += __ldg(&NWg[t * 256 + ocbase + 1]);
                }
            }
        }
        if (STAGE == 1) {
            uint32_t sb = 0;
#pragma unroll
            for (int j = 0; j < 2; j++) {
                uint32_t av = acc[p][j];
                int ones = (int)(av & 1023u) + 2 * (int)((av >> 10) & 2047u) + 4 * (int)(av >> 21);
                int dot = CTOT * nv - 2 * ones + 2 * corr[j];
                float val = (float)dot * alpha[j] + cc[j];
                val += Rs[(og * 2 + j) * 57 + xx];
                val = fminf(fmaxf(val, -1.f), 1.f);
                Vs[(og * 2 + j) * 57 + xx] = val;
                sb |= (val < 0.f ? 1u : 0u) << j;
            }
            stg[xx * 32 + og] = sb;
        } else {
#pragma unroll
            for (int j = 0; j < 2; j++) {
                uint32_t av = acc[p][j];
                int ones = (int)(av & 1023u) + 2 * (int)((av >> 10) & 2047u) + 4 * (int)(av >> 21);
                int dot = CTOT * nv - 2 * ones + 2 * corr[j];
                Vs[(og * 2 + j) * 57 + xx] = (float)dot * alpha[j] + cc[j];
            }
        }
    }
    __syncthreads();

    // ---- coalesced writeout ----
    if (STAGE == 1) {
        if (ocq < 2) {
            for (int idx = tid; idx < 64 * WW; idx += 256) {
                int oc_l = idx / WW, px = idx % WW;
                g_Out1f[(((size_t)b * 128 + ocq * 64 + oc_l) * HH + y) * WW + px] =
                    Vs[oc_l * 57 + px];
            }
        }
        if (tid < 2 * WW) {
            int px = tid >> 1, wsel = tid & 1;
            uint32_t word = 0;
#pragma unroll
            for (int q = 0; q < 16; q++) {
                uint32_t v = stg[px * 32 + wsel * 16 + q];
                word |= (v & 1u) << (2 * q);
                word |= ((v >> 1) & 1u) << (2 * q + 1);
            }
            g_Sbits[((b * 16 + (ocq * 2 + wsel)) * HH + y) * WW + px] = word;
        }
    } else {
        for (int idx = tid; idx < 64 * WW; idx += 256) {
            int oc_l = idx / WW, px = idx % WW;
            int oc = ocq * 64 + oc_l;
            float v = Vs[oc_l * 57 + px];
            float res;
            if ((oc & 1) == 0)
                res = __ldg(&g_Out1f[(((size_t)b * 128 + (oc >> 1)) * HH + y) * WW + px]);
            else
                res = __ldg(&x[(((size_t)b * 512 + 256 + (oc >> 1)) * HH + y) * WW + px]) +
                      __ldg(&mb[oc >> 1]);
            v = fminf(fmaxf(v + res, -1.f), 1.f);
            out[(((size_t)b * 256 + oc) * HH + y) * WW + px] = v;
        }
    }
}

// ---------------- launch ----------------
extern "C" void kernel_launch(void* const* d_in, const int* in_sizes, int n_in,
                              void* d_out, int out_size) {
    const float* x      = (const float*)d_in[0];
    const float* w1     = (const float*)d_in[1];
    const float* w2     = (const float*)d_in[2];
    const float* gamma1 = (const float*)d_in[3];
    const float* beta1  = (const float*)d_in[4];
    const float* mean1  = (const float*)d_in[5];
    const float* var1   = (const float*)d_in[6];
    const float* gamma2 = (const float*)d_in[7];
    const float* beta2  = (const float*)d_in[8];
    const float* mean2  = (const float*)d_in[9];
    const float* var2   = (const float*)d_in[10];
    const float* mb     = (const float*)d_in[11];
    float* out = (float*)d_out;

    const int smem1 = (72 * 64 + 8 * 3 * 58 + 64 * 57) * 4;   // 38592 B
    const int smem2 = (144 * 64 + 16 * 3 * 58) * 4;           // 48000 B
    cudaFuncSetAttribute(binconv<8, 1>,  cudaFuncAttributeMaxDynamicSharedMemorySize, smem1);
    cudaFuncSetAttribute(binconv<16, 2>, cudaFuncAttributeMaxDynamicSharedMemorySize, smem2);

    prep_w1<<<256, 256>>>(w1, gamma1, beta1, mean1, var1);
    prep_w2<<<256, 256>>>(w2, gamma2, beta2, mean2, var2);
    pack_input<<<(BATCH * HH * WW + 255) / 256, 256>>>(x, mb);

    dim3 grid(4, HH, BATCH);
    binconv<8, 1><<<grid, 256, smem1>>>(x, mb, out);
    binconv<16, 2><<<grid, 256, smem2>>>(x, mb, out);
}

// round 6
// speedup vs baseline: 1.0114x; 1.0114x over previous
#include <cuda_runtime.h>
#include <cstdint>

#define BATCH 16
#define HH 56
#define WW 56
#define EPSV 1e-5f

// ---------------- scratch (device globals; no allocation) ----------------
__device__ uint32_t g_Abits[BATCH * 8 * HH * WW];    // stage1 input bits  [b][w][y][x]
__device__ uint32_t g_Sbits[BATCH * 16 * HH * WW];   // stage2 input bits  [b][w][y][x]
__device__ float    g_Out1f[BATCH * 128 * HH * WW];  // out1 channels 0..127
__device__ uint32_t g_W1b[72 * 256];                 // [k][oc]
__device__ uint32_t g_W2b[144 * 256];                // permuted for shuffle
__device__ int      g_NW1[9 * 256];
__device__ int      g_NW2[9 * 256];
__device__ float    g_alpha1[256], g_c1[256], g_alpha2[256], g_c2[256];

// ---------------- weight prep ----------------
__global__ void prep_w1(const float* __restrict__ w1, const float* __restrict__ gm,
                        const float* __restrict__ bt, const float* __restrict__ mn,
                        const float* __restrict__ vr) {
    int oc = blockIdx.x;
    int c  = threadIdx.x;
    int lane = c & 31, wi = c >> 5;
    __shared__ int nw[9];
    __shared__ float red[8];
    if (c < 9) nw[c] = 0;
    __syncthreads();
    float asum = 0.f;
#pragma unroll
    for (int r = 0; r < 3; r++)
#pragma unroll
        for (int dx = 0; dx < 3; dx++) {
            float v = w1[((oc * 256 + c) * 3 + r) * 3 + dx];
            asum += fabsf(v);
            unsigned word = __ballot_sync(0xffffffffu, v < 0.f);
            if (lane == 0) {
                int k = (wi * 3 + r) * 3 + dx;
                g_W1b[k * 256 + oc] = word;
                atomicAdd(&nw[r * 3 + dx], __popc(word));
            }
        }
    __syncthreads();
    if (c < 9) g_NW1[c * 256 + oc] = nw[c];
    for (int o = 16; o > 0; o >>= 1) asum += __shfl_xor_sync(0xffffffffu, asum, o);
    if (lane == 0) red[wi] = asum;
    __syncthreads();
    if (c == 0) {
        float s = 0.f;
#pragma unroll
        for (int i = 0; i < 8; i++) s += red[i];
        float scale = s / (256.f * 9.f);
        float inv = gm[oc] / sqrtf(vr[oc] + EPSV);
        g_alpha1[oc] = scale * inv;
        g_c1[oc] = bt[oc] - mn[oc] * inv;
    }
}

__global__ void prep_w2(const float* __restrict__ w2, const float* __restrict__ gm,
                        const float* __restrict__ bt, const float* __restrict__ mn,
                        const float* __restrict__ vr) {
    int oc = blockIdx.x;
    int c  = threadIdx.x;
    int lane = c & 31;
    __shared__ int nw[9];
    __shared__ float red[8];
    if (c < 9) nw[c] = 0;
    __syncthreads();
    float asum = 0.f;
    for (int it = 0; it < 2; it++) {
        int j  = it * 256 + c;
        int ic = (j < 256) ? (2 * j) : (2 * (j - 256) + 1);
        int wi = j >> 5;
#pragma unroll
        for (int r = 0; r < 3; r++)
#pragma unroll
            for (int dx = 0; dx < 3; dx++) {
                float v = w2[((oc * 512 + ic) * 3 + r) * 3 + dx];
                asum += fabsf(v);
                unsigned word = __ballot_sync(0xffffffffu, v < 0.f);
                if (lane == 0) {
                    int k = (wi * 3 + r) * 3 + dx;
                    g_W2b[k * 256 + oc] = word;
                    atomicAdd(&nw[r * 3 + dx], __popc(word));
                }
            }
    }
    __syncthreads();
    if (c < 9) g_NW2[c * 256 + oc] = nw[c];
    for (int o = 16; o > 0; o >>= 1) asum += __shfl_xor_sync(0xffffffffu, asum, o);
    if (lane == 0) red[c >> 5] = asum;
    __syncthreads();
    if (c == 0) {
        float s = 0.f;
#pragma unroll
        for (int i = 0; i < 8; i++) s += red[i];
        float scale = s / (512.f * 9.f);
        float inv = gm[oc] / sqrtf(vr[oc] + EPSV);
        g_alpha2[oc] = scale * inv;
        g_c2[oc] = bt[oc] - mn[oc] * inv;
    }
}

// ---------------- input packing ----------------
__global__ void pack_input(const float* __restrict__ x, const float* __restrict__ mb) {
    int n = blockIdx.x * blockDim.x + threadIdx.x;
    if (n >= BATCH * HH * WW) return;
    int xw = n % (HH * WW);
    int b  = n / (HH * WW);
    const float* xp = x + (size_t)b * 512 * HH * WW + xw;
#pragma unroll 1
    for (int wi = 0; wi < 8; wi++) {
        uint32_t word = 0;
#pragma unroll
        for (int k = 0; k < 32; k++) {
            float v = __ldg(&xp[(size_t)(wi * 32 + k) * HH * WW]);
            word |= (v < 0.f ? 1u : 0u) << k;
        }
        g_Abits[(b * 8 + wi) * HH * WW + xw] = word;
    }
#pragma unroll 1
    for (int wi = 0; wi < 8; wi++) {
        uint32_t word = 0;
#pragma unroll
        for (int k = 0; k < 32; k++) {
            int ci = wi * 32 + k;
            float v = __ldg(&xp[(size_t)(256 + ci) * HH * WW]) + __ldg(&mb[ci]);
            word |= (v < 0.f ? 1u : 0u) << k;
        }
        g_Sbits[(b * 16 + (8 + wi)) * HH * WW + xw] = word;
    }
}

__device__ __forceinline__ uint32_t maj3(uint32_t a, uint32_t b, uint32_t c) {
    return (a & b) | (b & c) | (a & c);   // single LOP3, LUT 0xE8
}
__device__ __forceinline__ uint32_t xor3(uint32_t a, uint32_t b, uint32_t c) {
    return a ^ b ^ c;                      // single LOP3, LUT 0x96
}

// ---------------- binarized conv (XOR + 9:4 CSA, 1 oc/thread) ------------
// Block: 256 threads (8 warps); tile = 56 px (one row) x 32 oc.
// Thread: 7 px x 1 oc (lane = oc). Sign repack via warp ballot.
// Packed acc: bit0 (S1, <=512), bit10 (C1+S2, <=1024), bit21 (C2, <=512).
template <int WORDS, int STAGE>
__global__ __launch_bounds__(256, 4) void binconv(const float* __restrict__ x,
                                                  const float* __restrict__ mb,
                                                  float* __restrict__ out) {
    constexpr int K = WORDS * 9;
    constexpr int CTOT = WORDS * 32;
    extern __shared__ uint32_t smem[];
    uint32_t* Ws = smem;                          // [K][32]  (reused post-mainloop)
    uint32_t* As = smem + K * 32;                 // [WORDS*3][58]
    float*    Rs = (float*)(As + WORDS * 3 * 58); // stage1: [32][57] residual -> Vs
    float*    Vs = (STAGE == 1) ? Rs : (float*)Ws;

    const uint32_t* Gb = (STAGE == 1) ? g_Abits : g_Sbits;
    const uint32_t* Wg = (STAGE == 1) ? g_W1b : g_W2b;

    int ocq = blockIdx.x;        // oc word (32 oc)
    int y = blockIdx.y;
    int b = blockIdx.z;
    int tid = threadIdx.x;
    int lane = tid & 31;         // oc within word
    int g  = tid >> 5;           // warp: pixel group (7 px)

    // ---- cooperative loads ----
    for (int idx = tid; idx < K * 32; idx += 256) {
        int k = idx >> 5, o = idx & 31;
        Ws[idx] = Wg[k * 256 + ocq * 32 + o];
    }
    for (int idx = tid; idx < WORDS * 3 * 58; idx += 256) {
        int c = idx % 58;
        int wr = idx / 58;
        int r = wr % 3, w = wr / 3;
        int yy = y + r - 1;
        int xx = c - 1;
        uint32_t v = 0;
        if ((unsigned)yy < HH && (unsigned)xx < WW)
            v = Gb[((b * WORDS + w) * HH + yy) * WW + xx];
        As[wr * 58 + c] = v;
    }
    if (STAGE == 1) {
        for (int idx = tid; idx < 32 * WW; idx += 256) {
            int oc_l = idx / WW, px = idx % WW;
            Rs[oc_l * 57 + px] =
                __ldg(&x[(((size_t)b * 512 + ocq * 32 + oc_l) * HH + y) * WW + px]);
        }
    }
    __syncthreads();

    // ---- main loop ----
    uint32_t acc[7];
#pragma unroll
    for (int p = 0; p < 7; p++) acc[p] = 0;

#pragma unroll 1
    for (int w = 0; w < WORDS; w++) {
        uint32_t A0[9], A1[9], A2[9];
        {
            const uint32_t* r0 = &As[(w * 3 + 0) * 58 + 7 * g];
            const uint32_t* r1 = &As[(w * 3 + 1) * 58 + 7 * g];
            const uint32_t* r2 = &As[(w * 3 + 2) * 58 + 7 * g];
#pragma unroll
            for (int i = 0; i < 9; i++) { A0[i] = r0[i]; A1[i] = r1[i]; A2[i] = r2[i]; }
        }
        uint32_t wv[9];
#pragma unroll
        for (int k = 0; k < 9; k++) wv[k] = Ws[(w * 9 + k) * 32 + lane];
#pragma unroll
        for (int p = 0; p < 7; p++) {
            uint32_t x0, x1, x2;
            x0 = A0[p] ^ wv[0]; x1 = A0[p + 1] ^ wv[1]; x2 = A0[p + 2] ^ wv[2];
            uint32_t s0 = xor3(x0, x1, x2), c0 = maj3(x0, x1, x2);
            x0 = A1[p] ^ wv[3]; x1 = A1[p + 1] ^ wv[4]; x2 = A1[p + 2] ^ wv[5];
            uint32_t s1 = xor3(x0, x1, x2), c1 = maj3(x0, x1, x2);
            x0 = A2[p] ^ wv[6]; x1 = A2[p + 1] ^ wv[7]; x2 = A2[p + 2] ^ wv[8];
            uint32_t s2 = xor3(x0, x1, x2), c2 = maj3(x0, x1, x2);
            uint32_t S1 = xor3(s0, s1, s2), C1 = maj3(s0, s1, s2);
            uint32_t S2 = xor3(c0, c1, c2), C2 = maj3(c0, c1, c2);
            uint32_t t = acc[p];
            t += __popc(S1);                        // IADD (alu)
            t = __popc(C1) * 1024u + t;             // IMAD (fma)
            t = __popc(S2) * 1024u + t;             // IMAD (fma)
            t = __popc(C2) * (1u << 21) + t;        // IMAD (fma)
            acc[p] = t;
        }
    }
    __syncthreads();   // Ws reads done; region reusable

    // ---- epilogue ----
    int oc = ocq * 32 + lane;
    const float* Ag = (STAGE == 1) ? g_alpha1 : g_alpha2;
    const float* Cg = (STAGE == 1) ? g_c1 : g_c2;
    const int* NWg = (STAGE == 1) ? g_NW1 : g_NW2;
    float alpha = __ldg(&Ag[oc]);
    float cc    = __ldg(&Cg[oc]);
    bool ybord = (y == 0) || (y == HH - 1);

    uint32_t* sb_out = &g_Sbits[((b * 16 + ocq) * HH + y) * WW];

#pragma unroll
    for (int p = 0; p < 7; p++) {
        int xx = 7 * g + p;
        bool bord = ybord || (xx == 0) || (xx == WW - 1);
        int nv = 9;
        int corr = 0;
        if (bord) {
#pragma unroll
            for (int t = 0; t < 9; t++) {
                int dy = t / 3 - 1, dx = t % 3 - 1;
                if ((unsigned)(y + dy) >= HH || (unsigned)(xx + dx) >= WW) {
                    nv--;
                    corr += __ldg(&NWg[t * 256 + oc]);
                }
            }
        }
        uint32_t av = acc[p];
        int ones = (int)(av & 1023u) + 2 * (int)((av >> 10) & 2047u) + 4 * (int)(av >> 21);
        int dot = CTOT * nv - 2 * ones + 2 * corr;
        float val = (float)dot * alpha + cc;
        if (STAGE == 1) {
            val += Rs[lane * 57 + xx];
            val = fminf(fmaxf(val, -1.f), 1.f);
            Vs[lane * 57 + xx] = val;
            uint32_t word = __ballot_sync(0xffffffffu, val < 0.f);
            if (lane == 0) sb_out[xx] = word;
        } else {
            Vs[lane * 57 + xx] = val;
        }
    }
    __syncthreads();

    // ---- coalesced writeout ----
    if (STAGE == 1) {
        if (ocq < 4) {   // float out1 needed only for oc < 128
            for (int idx = tid; idx < 32 * WW; idx += 256) {
                int oc_l = idx / WW, px = idx % WW;
                g_Out1f[(((size_t)b * 128 + ocq * 32 + oc_l) * HH + y) * WW + px] =
                    Vs[oc_l * 57 + px];
            }
        }
    } else {
        for (int idx = tid; idx < 32 * WW; idx += 256) {
            int oc_l = idx / WW, px = idx % WW;
            int oco = ocq * 32 + oc_l;
            float v = Vs[oc_l * 57 + px];
            float res;
            if ((oco & 1) == 0)
                res = __ldg(&g_Out1f[(((size_t)b * 128 + (oco >> 1)) * HH + y) * WW + px]);
            else
                res = __ldg(&x[(((size_t)b * 512 + 256 + (oco >> 1)) * HH + y) * WW + px]) +
                      __ldg(&mb[oco >> 1]);
            v = fminf(fmaxf(v + res, -1.f), 1.f);
            out[(((size_t)b * 256 + oco) * HH + y) * WW + px] = v;
        }
    }
}

// ---------------- launch ----------------
extern "C" void kernel_launch(void* const* d_in, const int* in_sizes, int n_in,
                              void* d_out, int out_size) {
    const float* x      = (const float*)d_in[0];
    const float* w1     = (const float*)d_in[1];
    const float* w2     = (const float*)d_in[2];
    const float* gamma1 = (const float*)d_in[3];
    const float* beta1  = (const float*)d_in[4];
    const float* mean1  = (const float*)d_in[5];
    const float* var1   = (const float*)d_in[6];
    const float* gamma2 = (const float*)d_in[7];
    const float* beta2  = (const float*)d_in[8];
    const float* mean2  = (const float*)d_in[9];
    const float* var2   = (const float*)d_in[10];
    const float* mb     = (const float*)d_in[11];
    float* out = (float*)d_out;

    const int smem1 = (72 * 32 + 8 * 3 * 58 + 32 * 57) * 4;    // 22080 B
    const int smem2 = (144 * 32 + 16 * 3 * 58) * 4;            // 29568 B
    cudaFuncSetAttribute(binconv<8, 1>,  cudaFuncAttributeMaxDynamicSharedMemorySize, smem1);
    cudaFuncSetAttribute(binconv<16, 2>, cudaFuncAttributeMaxDynamicSharedMemorySize, smem2);

    prep_w1<<<256, 256>>>(w1, gamma1, beta1, mean1, var1);
    prep_w2<<<256, 256>>>(w2, gamma2, beta2, mean2, var2);
    pack_input<<<(BATCH * HH * WW + 255) / 256, 256>>>(x, mb);

    dim3 grid(8, HH, BATCH);
    binconv<8, 1><<<grid, 256, smem1>>>(x, mb, out);
    binconv<16, 2><<<grid, 256, smem2>>>(x, mb, out);
}

// round 7
// speedup vs baseline: 1.1205x; 1.1078x over previous
#include <cuda_runtime.h>
#include <cstdint>

#define BATCH 16
#define HH 56
#define WW 56
#define EPSV 1e-5f

// ---------------- scratch (device globals; no allocation) ----------------
__device__ uint32_t g_Abits[BATCH * 8 * HH * WW];    // stage1 input bits  [b][w][y][x]
__device__ uint32_t g_Sbits[BATCH * 16 * HH * WW];   // stage2 input bits  [b][w][y][x]
__device__ float    g_Out1f[BATCH * 128 * HH * WW];  // out1 channels 0..127
__device__ uint32_t g_W1b[72 * 256];                 // [k][oc]
__device__ uint32_t g_W2b[144 * 256];                // permuted for shuffle
__device__ int      g_NW1[9 * 256];
__device__ int      g_NW2[9 * 256];
__device__ float    g_alpha1[256], g_c1[256], g_alpha2[256], g_c2[256];

// ---------------- weight prep ----------------
__global__ void prep_w1(const float* __restrict__ w1, const float* __restrict__ gm,
                        const float* __restrict__ bt, const float* __restrict__ mn,
                        const float* __restrict__ vr) {
    int oc = blockIdx.x;
    int c  = threadIdx.x;
    int lane = c & 31, wi = c >> 5;
    __shared__ int nw[9];
    __shared__ float red[8];
    if (c < 9) nw[c] = 0;
    __syncthreads();
    float asum = 0.f;
#pragma unroll
    for (int r = 0; r < 3; r++)
#pragma unroll
        for (int dx = 0; dx < 3; dx++) {
            float v = w1[((oc * 256 + c) * 3 + r) * 3 + dx];
            asum += fabsf(v);
            unsigned word = __ballot_sync(0xffffffffu, v < 0.f);
            if (lane == 0) {
                int k = (wi * 3 + r) * 3 + dx;
                g_W1b[k * 256 + oc] = word;
                atomicAdd(&nw[r * 3 + dx], __popc(word));
            }
        }
    __syncthreads();
    if (c < 9) g_NW1[c * 256 + oc] = nw[c];
    for (int o = 16; o > 0; o >>= 1) asum += __shfl_xor_sync(0xffffffffu, asum, o);
    if (lane == 0) red[wi] = asum;
    __syncthreads();
    if (c == 0) {
        float s = 0.f;
#pragma unroll
        for (int i = 0; i < 8; i++) s += red[i];
        float scale = s / (256.f * 9.f);
        float inv = gm[oc] / sqrtf(vr[oc] + EPSV);
        g_alpha1[oc] = scale * inv;
        g_c1[oc] = bt[oc] - mn[oc] * inv;
    }
}

__global__ void prep_w2(const float* __restrict__ w2, const float* __restrict__ gm,
                        const float* __restrict__ bt, const float* __restrict__ mn,
                        const float* __restrict__ vr) {
    int oc = blockIdx.x;
    int c  = threadIdx.x;
    int lane = c & 31;
    __shared__ int nw[9];
    __shared__ float red[8];
    if (c < 9) nw[c] = 0;
    __syncthreads();
    float asum = 0.f;
    for (int it = 0; it < 2; it++) {
        int j  = it * 256 + c;
        int ic = (j < 256) ? (2 * j) : (2 * (j - 256) + 1);
        int wi = j >> 5;
#pragma unroll
        for (int r = 0; r < 3; r++)
#pragma unroll
            for (int dx = 0; dx < 3; dx++) {
                float v = w2[((oc * 512 + ic) * 3 + r) * 3 + dx];
                asum += fabsf(v);
                unsigned word = __ballot_sync(0xffffffffu, v < 0.f);
                if (lane == 0) {
                    int k = (wi * 3 + r) * 3 + dx;
                    g_W2b[k * 256 + oc] = word;
                    atomicAdd(&nw[r * 3 + dx], __popc(word));
                }
            }
    }
    __syncthreads();
    if (c < 9) g_NW2[c * 256 + oc] = nw[c];
    for (int o = 16; o > 0; o >>= 1) asum += __shfl_xor_sync(0xffffffffu, asum, o);
    if (lane == 0) red[c >> 5] = asum;
    __syncthreads();
    if (c == 0) {
        float s = 0.f;
#pragma unroll
        for (int i = 0; i < 8; i++) s += red[i];
        float scale = s / (512.f * 9.f);
        float inv = gm[oc] / sqrtf(vr[oc] + EPSV);
        g_alpha2[oc] = scale * inv;
        g_c2[oc] = bt[oc] - mn[oc] * inv;
    }
}

// ---------------- input packing ----------------
__global__ void pack_input(const float* __restrict__ x, const float* __restrict__ mb) {
    int n = blockIdx.x * blockDim.x + threadIdx.x;
    if (n >= BATCH * HH * WW) return;
    int xw = n % (HH * WW);
    int b  = n / (HH * WW);
    const float* xp = x + (size_t)b * 512 * HH * WW + xw;
#pragma unroll 1
    for (int wi = 0; wi < 8; wi++) {
        uint32_t word = 0;
#pragma unroll
        for (int k = 0; k < 32; k++) {
            float v = __ldg(&xp[(size_t)(wi * 32 + k) * HH * WW]);
            word |= (v < 0.f ? 1u : 0u) << k;
        }
        g_Abits[(b * 8 + wi) * HH * WW + xw] = word;
    }
#pragma unroll 1
    for (int wi = 0; wi < 8; wi++) {
        uint32_t word = 0;
#pragma unroll
        for (int k = 0; k < 32; k++) {
            int ci = wi * 32 + k;
            float v = __ldg(&xp[(size_t)(256 + ci) * HH * WW]) + __ldg(&mb[ci]);
            word |= (v < 0.f ? 1u : 0u) << k;
        }
        g_Sbits[(b * 16 + (8 + wi)) * HH * WW + xw] = word;
    }
}

__device__ __forceinline__ uint32_t maj3(uint32_t a, uint32_t b, uint32_t c) {
    return (a & b) | (b & c) | (a & c);   // single LOP3, LUT 0xE8
}
__device__ __forceinline__ uint32_t xor3(uint32_t a, uint32_t b, uint32_t c) {
    return a ^ b ^ c;                      // single LOP3, LUT 0x96
}

// ---------------- binarized conv (XOR + row CSA, 1 oc/thread) ------------
// Block: 256 threads (8 warps); tile = 56 px (one row) x 32 oc.
// Thread: 7 px x 1 oc (lane = oc). Per-row CSA (R4 math):
//   popc(x0)+popc(x1)+popc(x2) = popc(xor3)+2*popc(maj3)
// Packed acc: lo16 = sum popc(xor3), hi16 = sum popc(maj3).
template <int WORDS, int STAGE>
__global__ __launch_bounds__(256, 6) void binconv(const float* __restrict__ x,
                                                  const float* __restrict__ mb,
                                                  float* __restrict__ out) {
    constexpr int K = WORDS * 9;
    constexpr int CTOT = WORDS * 32;
    extern __shared__ uint32_t smem[];
    uint32_t* Ws = smem;                          // [K][32]  (reused post-mainloop)
    uint32_t* As = smem + K * 32;                 // [WORDS*3][58]
    float*    Rs = (float*)(As + WORDS * 3 * 58); // stage1: [32][57] residual -> Vs
    float*    Vs = (STAGE == 1) ? Rs : (float*)Ws;

    const uint32_t* Gb = (STAGE == 1) ? g_Abits : g_Sbits;
    const uint32_t* Wg = (STAGE == 1) ? g_W1b : g_W2b;

    int ocq = blockIdx.x;        // oc word (32 oc)
    int y = blockIdx.y;
    int b = blockIdx.z;
    int tid = threadIdx.x;
    int lane = tid & 31;         // oc within word
    int g  = tid >> 5;           // warp: pixel group (7 px)

    // ---- cooperative loads ----
    for (int idx = tid; idx < K * 32; idx += 256) {
        int k = idx >> 5, o = idx & 31;
        Ws[idx] = Wg[k * 256 + ocq * 32 + o];
    }
    for (int idx = tid; idx < WORDS * 3 * 58; idx += 256) {
        int c = idx % 58;
        int wr = idx / 58;
        int r = wr % 3, w = wr / 3;
        int yy = y + r - 1;
        int xx = c - 1;
        uint32_t v = 0;
        if ((unsigned)yy < HH && (unsigned)xx < WW)
            v = Gb[((b * WORDS + w) * HH + yy) * WW + xx];
        As[wr * 58 + c] = v;
    }
    if (STAGE == 1) {
        for (int idx = tid; idx < 32 * WW; idx += 256) {
            int oc_l = idx / WW, px = idx % WW;
            Rs[oc_l * 57 + px] =
                __ldg(&x[(((size_t)b * 512 + ocq * 32 + oc_l) * HH + y) * WW + px]);
        }
    }
    __syncthreads();

    // ---- main loop (per-row CSA, packed acc) ----
    uint32_t acc[7];
#pragma unroll
    for (int p = 0; p < 7; p++) acc[p] = 0;

#pragma unroll 1
    for (int w = 0; w < WORDS; w++) {
#pragma unroll
        for (int r = 0; r < 3; r++) {
            const uint32_t* arow = &As[(w * 3 + r) * 58 + 7 * g];
            uint32_t a[9];
#pragma unroll
            for (int i = 0; i < 9; i++) a[i] = arow[i];
            int k0 = (w * 3 + r) * 3;
            uint32_t w0 = Ws[(k0 + 0) * 32 + lane];
            uint32_t w1 = Ws[(k0 + 1) * 32 + lane];
            uint32_t w2 = Ws[(k0 + 2) * 32 + lane];
#pragma unroll
            for (int p = 0; p < 7; p++) {
                uint32_t x0 = a[p] ^ w0, x1 = a[p + 1] ^ w1, x2 = a[p + 2] ^ w2;
                uint32_t t = acc[p];
                t = __popc(maj3(x0, x1, x2)) * 65536u + t;   // IMAD (fma pipe)
                t += __popc(xor3(x0, x1, x2));               // IADD (alu)
                acc[p] = t;
            }
        }
    }
    __syncthreads();   // Ws reads done; region reusable

    // ---- epilogue ----
    int oc = ocq * 32 + lane;
    const float* Ag = (STAGE == 1) ? g_alpha1 : g_alpha2;
    const float* Cg = (STAGE == 1) ? g_c1 : g_c2;
    const int* NWg = (STAGE == 1) ? g_NW1 : g_NW2;
    float alpha = __ldg(&Ag[oc]);
    float cc    = __ldg(&Cg[oc]);
    bool ybord = (y == 0) || (y == HH - 1);

    uint32_t* sb_out = &g_Sbits[((b * 16 + ocq) * HH + y) * WW];

#pragma unroll
    for (int p = 0; p < 7; p++) {
        int xx = 7 * g + p;
        bool bord = ybord || (xx == 0) || (xx == WW - 1);
        int nv = 9;
        int corr = 0;
        if (bord) {
#pragma unroll
            for (int t = 0; t < 9; t++) {
                int dy = t / 3 - 1, dx = t % 3 - 1;
                if ((unsigned)(y + dy) >= HH || (unsigned)(xx + dx) >= WW) {
                    nv--;
                    corr += __ldg(&NWg[t * 256 + oc]);
                }
            }
        }
        uint32_t av = acc[p];
        int ones = (int)(av & 0xFFFFu) + 2 * (int)(av >> 16);
        int dot = CTOT * nv - 2 * ones + 2 * corr;
        float val = (float)dot * alpha + cc;
        if (STAGE == 1) {
            val += Rs[lane * 57 + xx];
            val = fminf(fmaxf(val, -1.f), 1.f);
            Vs[lane * 57 + xx] = val;
            uint32_t word = __ballot_sync(0xffffffffu, val < 0.f);
            if (lane == 0) sb_out[xx] = word;
        } else {
            Vs[lane * 57 + xx] = val;
        }
    }
    __syncthreads();

    // ---- coalesced writeout ----
    if (STAGE == 1) {
        if (ocq < 4) {   // float out1 needed only for oc < 128
            for (int idx = tid; idx < 32 * WW; idx += 256) {
                int oc_l = idx / WW, px = idx % WW;
                g_Out1f[(((size_t)b * 128 + ocq * 32 + oc_l) * HH + y) * WW + px] =
                    Vs[oc_l * 57 + px];
            }
        }
    } else {
        for (int idx = tid; idx < 32 * WW; idx += 256) {
            int oc_l = idx / WW, px = idx % WW;
            int oco = ocq * 32 + oc_l;
            float v = Vs[oc_l * 57 + px];
            float res;
            if ((oco & 1) == 0)
                res = __ldg(&g_Out1f[(((size_t)b * 128 + (oco >> 1)) * HH + y) * WW + px]);
            else
                res = __ldg(&x[(((size_t)b * 512 + 256 + (oco >> 1)) * HH + y) * WW + px]) +
                      __ldg(&mb[oco >> 1]);
            v = fminf(fmaxf(v + res, -1.f), 1.f);
            out[(((size_t)b * 256 + oco) * HH + y) * WW + px] = v;
        }
    }
}

// ---------------- launch ----------------
extern "C" void kernel_launch(void* const* d_in, const int* in_sizes, int n_in,
                              void* d_out, int out_size) {
    const float* x      = (const float*)d_in[0];
    const float* w1     = (const float*)d_in[1];
    const float* w2     = (const float*)d_in[2];
    const float* gamma1 = (const float*)d_in[3];
    const float* beta1  = (const float*)d_in[4];
    const float* mean1  = (const float*)d_in[5];
    const float* var1   = (const float*)d_in[6];
    const float* gamma2 = (const float*)d_in[7];
    const float* beta2  = (const float*)d_in[8];
    const float* mean2  = (const float*)d_in[9];
    const float* var2   = (const float*)d_in[10];
    const float* mb     = (const float*)d_in[11];
    float* out = (float*)d_out;

    const int smem1 = (72 * 32 + 8 * 3 * 58 + 32 * 57) * 4;    // 22080 B
    const int smem2 = (144 * 32 + 16 * 3 * 58) * 4;            // 29568 B
    cudaFuncSetAttribute(binconv<8, 1>,  cudaFuncAttributeMaxDynamicSharedMemorySize, smem1);
    cudaFuncSetAttribute(binconv<16, 2>, cudaFuncAttributeMaxDynamicSharedMemorySize, smem2);

    prep_w1<<<256, 256>>>(w1, gamma1, beta1, mean1, var1);
    prep_w2<<<256, 256>>>(w2, gamma2, beta2, mean2, var2);
    pack_input<<<(BATCH * HH * WW + 255) / 256, 256>>>(x, mb);

    dim3 grid(8, HH, BATCH);
    binconv<8, 1><<<grid, 256, smem1>>>(x, mb, out);
    binconv<16, 2><<<grid, 256, smem2>>>(x, mb, out);
}